// round 4
// baseline (speedup 1.0000x reference)
#include <cuda_runtime.h>

// ----------------------------------------------------------------------------
// PeriodicPrimitives2D: out[i,ch] = sum_g  g(i,g) * wx(i,g) * wy(i,g) * col[g,ch]
//   tx =  dx*cos + dy*sin ; ty = -dx*sin + dy*cos
//   g  = exp(-0.5*((tx*e^sx)^2 + (ty*e^sy)^2))
//   wx = sum_k cx_k * cos(2*pi*tx*fx_k),  f = int_index * (1024/1024)  (integer!)
// ----------------------------------------------------------------------------

#define MAX_G 4096
#define TILE  256

typedef unsigned long long u64;

// Packed per-gaussian data (written by prep kernel)
__device__ float4 gA [MAX_G];       // px, py, cos(rot), sin(rot)
__device__ float4 gB [MAX_G];       // inv_sx, inv_sy, col0, col1
__device__ float  gC2[MAX_G];       // col2
__device__ float4 gFr[MAX_G * 2];   // (fx0,fy0,fx1,fy1),(fx2,fy2,fx3,fy3)
__device__ float4 gCf[MAX_G * 2];   // (cx0,cy0,cx1,cy1),(cx2,cy2,cx3,cy3)

// ---------------- f32x2 packed helpers (Blackwell full-rate FP32x2) ----------
__device__ __forceinline__ u64 pk2(float a, float b) {
    u64 r;
    asm("mov.b64 %0, {%1, %2};" : "=l"(r)
        : "r"(__float_as_uint(a)), "r"(__float_as_uint(b)));
    return r;
}
__device__ __forceinline__ void upk2(u64 v, float& a, float& b) {
    unsigned int lo, hi;
    asm("mov.b64 {%0, %1}, %2;" : "=r"(lo), "=r"(hi) : "l"(v));
    a = __uint_as_float(lo);
    b = __uint_as_float(hi);
}
__device__ __forceinline__ u64 mul2(u64 a, u64 b) {
    u64 r; asm("mul.rn.f32x2 %0, %1, %2;" : "=l"(r) : "l"(a), "l"(b)); return r;
}
__device__ __forceinline__ u64 add2(u64 a, u64 b) {
    u64 r; asm("add.rn.f32x2 %0, %1, %2;" : "=l"(r) : "l"(a), "l"(b)); return r;
}
__device__ __forceinline__ u64 fma2(u64 a, u64 b, u64 c) {
    u64 r; asm("fma.rn.f32x2 %0, %1, %2, %3;" : "=l"(r) : "l"(a), "l"(b), "l"(c));
    return r;
}

// Packed constants
#define C2v   0x4B4000004B400000ULL  // 1.5 * 2^23 (round-to-int magic), both lanes
#define nC2v  0xCB400000CB400000ULL  // -1.5 * 2^23
#define NEG1v 0xBF800000BF800000ULL  // -1.0f, both lanes
#define PI2v  0x40C90FDB40C90FDBULL  // 2*pi (fp32), both lanes

// One k-term for both dims: acc += (cx,cy) * cos(2*pi * (tx,ty) * (fx,fy))
// Exact phase-mod-1 via Dekker 2-prod + magic rounding (f is an integer).
__device__ __forceinline__ void costerm(u64 t2, u64 nt2,
                                        float fx, float fy,
                                        float cx, float cy, u64& acc) {
    u64 f2  = pk2(fx, fy);
    u64 hi  = mul2(t2, f2);             // fl(t*f)
    u64 m   = fma2(nt2, f2, hi);        // hi - t*f   (= -lo, exact)
    u64 u   = add2(hi, C2v);
    u64 r   = add2(u, nC2v);            // nearest integer to hi
    u64 d   = fma2(r, NEG1v, hi);       // hi - r   in [-0.5, 0.5]
    u64 ph  = fma2(m, NEG1v, d);        // (hi - r) + lo  == t*f mod 1 (centered)
    u64 ar  = mul2(ph, PI2v);           // radians, |ar| <= ~4.4
    float ax, ay; upk2(ar, ax, ay);
    float vx = __cosf(ax);
    float vy = __cosf(ay);
    acc = fma2(pk2(vx, vy), pk2(cx, cy), acc);
}

// ---------------- prep: fold per-gaussian transcendentals, repack SoA --------
__global__ void prep_kernel(const float* __restrict__ colors,
                            const float* __restrict__ pos,
                            const float* __restrict__ scales,
                            const float* __restrict__ rots,
                            const float* __restrict__ coeffs,
                            const int*   __restrict__ indices,
                            int G) {
    int g = blockIdx.x * blockDim.x + threadIdx.x;
    if (g >= G) return;
    float s, c;
    sincosf(rots[g], &s, &c);
    gA[g]  = make_float4(pos[2 * g], pos[2 * g + 1], c, s);
    gB[g]  = make_float4(expf(scales[2 * g]), expf(scales[2 * g + 1]),
                         colors[3 * g], colors[3 * g + 1]);
    gC2[g] = colors[3 * g + 2];

    const float FS = 1024.0f / 1024.0f;  // max_frequency / num_frequencies
    float fx[4], fy[4], cx[4], cy[4];
#pragma unroll
    for (int k = 0; k < 4; k++) {
        fx[k] = (float)indices[(g * 4 + k) * 2 + 0] * FS;
        fy[k] = (float)indices[(g * 4 + k) * 2 + 1] * FS;
        cx[k] = coeffs[(g * 4 + k) * 2 + 0];
        cy[k] = coeffs[(g * 4 + k) * 2 + 1];
    }
    gFr[2 * g + 0] = make_float4(fx[0], fy[0], fx[1], fy[1]);
    gFr[2 * g + 1] = make_float4(fx[2], fy[2], fx[3], fy[3]);
    gCf[2 * g + 0] = make_float4(cx[0], cy[0], cx[1], cy[1]);
    gCf[2 * g + 1] = make_float4(cx[2], cy[2], cx[3], cy[3]);
}

// ---------------- render: 1 thread = 1 pixel, smem tiles of gaussians --------
__global__ __launch_bounds__(256)
void render_kernel(const float* __restrict__ x, float* __restrict__ out,
                   int N, int G) {
    __shared__ float4 sA [TILE];
    __shared__ float4 sB [TILE];
    __shared__ float  sC2[TILE];
    __shared__ float4 sFr[TILE * 2];
    __shared__ float4 sCf[TILE * 2];

    int tid = threadIdx.x;
    int i   = blockIdx.x * 256 + tid;
    float px = 0.0f, py = 0.0f;
    if (i < N) {
        float2 p = reinterpret_cast<const float2*>(x)[i];
        px = p.x; py = p.y;
    }
    float a0 = 0.0f, a1 = 0.0f, a2 = 0.0f;

    for (int t0 = 0; t0 < G; t0 += TILE) {
        int gi = t0 + tid;
        if (gi < G) {
            sA [tid]         = gA [gi];
            sB [tid]         = gB [gi];
            sC2[tid]         = gC2[gi];
            sFr[2 * tid]     = gFr[2 * gi];
            sFr[2 * tid + 1] = gFr[2 * gi + 1];
            sCf[2 * tid]     = gCf[2 * gi];
            sCf[2 * tid + 1] = gCf[2 * gi + 1];
        }
        __syncthreads();

        int cnt = min(TILE, G - t0);
#pragma unroll 2
        for (int j = 0; j < cnt; j++) {
            float4 A = sA[j];
            float dx = px - A.x;
            float dy = py - A.y;
            float tx = fmaf(dy, A.w, dx * A.z);   //  dx*cos + dy*sin
            float ty = fmaf(dy, A.z, -dx * A.w);  // -dx*sin + dy*cos

            float4 B  = sB[j];
            float axv = tx * B.x;
            float ayv = ty * B.y;
            float sq  = fmaf(ayv, ayv, axv * axv);
            float gw  = __expf(-0.5f * sq);

            u64 t2  = pk2(tx, ty);
            u64 nt2 = pk2(-tx, -ty);
            u64 acc = 0ULL;  // (0.0f, 0.0f)

            float4 F0 = sFr[2 * j], F1 = sFr[2 * j + 1];
            float4 K0 = sCf[2 * j], K1 = sCf[2 * j + 1];
            costerm(t2, nt2, F0.x, F0.y, K0.x, K0.y, acc);
            costerm(t2, nt2, F0.z, F0.w, K0.z, K0.w, acc);
            costerm(t2, nt2, F1.x, F1.y, K1.x, K1.y, acc);
            costerm(t2, nt2, F1.z, F1.w, K1.z, K1.w, acc);

            float wx, wy; upk2(acc, wx, wy);
            float w = gw * wx * wy;
            a0 = fmaf(w, B.z,   a0);
            a1 = fmaf(w, B.w,   a1);
            a2 = fmaf(w, sC2[j], a2);
        }
        __syncthreads();
    }

    if (i < N) {
        out[3 * i + 0] = a0;
        out[3 * i + 1] = a1;
        out[3 * i + 2] = a2;
    }
}

// ---------------- harness entry ---------------------------------------------
extern "C" void kernel_launch(void* const* d_in, const int* in_sizes, int n_in,
                              void* d_out, int out_size) {
    const float* x       = (const float*)d_in[0];  // [N,2]
    const float* colors  = (const float*)d_in[1];  // [G,3]
    const float* pos     = (const float*)d_in[2];  // [G,2]
    const float* scales  = (const float*)d_in[3];  // [G,2]
    const float* rots    = (const float*)d_in[4];  // [G,1]
    const float* coeffs  = (const float*)d_in[5];  // [G,4,2]
    const int*   indices = (const int*)  d_in[6];  // [G,4,2]

    int N = in_sizes[0] / 2;
    int G = in_sizes[1] / 3;
    if (G > MAX_G) G = MAX_G;

    prep_kernel<<<(G + 255) / 256, 256>>>(colors, pos, scales, rots,
                                          coeffs, indices, G);
    render_kernel<<<(N + 255) / 256, 256>>>(x, (float*)d_out, N, G);
}

// round 5
// speedup vs baseline: 1.2319x; 1.2319x over previous
#include <cuda_runtime.h>

// ----------------------------------------------------------------------------
// PeriodicPrimitives2D
//   out[i,ch] = sum_g exp(-0.5*((tx*e^sx)^2+(ty*e^sy)^2)) * wx * wy * col[g,ch]
//   wx = sum_k cx_k * cos(2*pi*tx*fx_k), fx integer-valued.
// Strategy: all per-gaussian transcendentals folded by a prep kernel; render
// kernel is packed-f32x2 math, exact phase reduction via fma+magic, MUFU
// cos/ex2. Target: MUFU-pipe bound (~72 SMSP cyc per warp-pair).
// ----------------------------------------------------------------------------

#define MAX_G 4096
#define TILE  256

typedef unsigned long long u64;

// Per-gaussian packed data (written by prep kernel)
__device__ float4 dP [MAX_G];       // c, -s, s, c
__device__ float4 dQ [MAX_G];       // -ox, -oy, sx', sy'   (s' = e^scale * sqrt(0.5*log2e))
__device__ float4 dC [MAX_G];       // col0, col1, col2, 0
__device__ float4 dFK[MAX_G * 4];   // fx_k, fy_k, cx_k, cy_k

// ---------------- f32x2 packed helpers --------------------------------------
__device__ __forceinline__ u64 pk2(float a, float b) {
    u64 r;
    asm("mov.b64 %0, {%1, %2};" : "=l"(r)
        : "r"(__float_as_uint(a)), "r"(__float_as_uint(b)));
    return r;
}
__device__ __forceinline__ void upk2(u64 v, float& a, float& b) {
    unsigned int lo, hi;
    asm("mov.b64 {%0, %1}, %2;" : "=r"(lo), "=r"(hi) : "l"(v));
    a = __uint_as_float(lo);
    b = __uint_as_float(hi);
}
__device__ __forceinline__ u64 mul2(u64 a, u64 b) {
    u64 r; asm("mul.rn.f32x2 %0, %1, %2;" : "=l"(r) : "l"(a), "l"(b)); return r;
}
__device__ __forceinline__ u64 fma2(u64 a, u64 b, u64 c) {
    u64 r; asm("fma.rn.f32x2 %0, %1, %2, %3;" : "=l"(r) : "l"(a), "l"(b), "l"(c));
    return r;
}
__device__ __forceinline__ float ex2(float x) {
    float r; asm("ex2.approx.f32 %0, %1;" : "=f"(r) : "f"(x)); return r;
}
__device__ __forceinline__ float cosap(float x) {
    float r; asm("cos.approx.f32 %0, %1;" : "=f"(r) : "f"(x)); return r;
}

// Packed constants
#define C2v   0x4B4000004B400000ULL  //  1.5 * 2^23 (round-to-int magic)
#define NEG1v 0xBF800000BF800000ULL  // -1.0f
#define PI2v  0x40C90FDB40C90FDBULL  //  2*pi

// ---------------- prep: fold per-gaussian transcendentals, repack -----------
__global__ void prep_kernel(const float* __restrict__ colors,
                            const float* __restrict__ pos,
                            const float* __restrict__ scales,
                            const float* __restrict__ rots,
                            const float* __restrict__ coeffs,
                            const int*   __restrict__ indices,
                            int G) {
    int g = blockIdx.x * blockDim.x + threadIdx.x;
    if (g >= G) return;
    float s, c;
    sincosf(rots[g], &s, &c);
    float gx = pos[2 * g], gy = pos[2 * g + 1];
    float ox =  gx * c + gy * s;
    float oy = -gx * s + gy * c;
    // s' = e^scale * sqrt(0.5 * log2(e))  so that  exp(-0.5*(t*e^s)^2) = 2^(-(t*s')^2)
    const float SCL = 0.84932180625508979f;  // sqrt(0.5 * 1.4426950408889634)
    dP[g] = make_float4(c, -s, s, c);
    dQ[g] = make_float4(-ox, -oy, expf(scales[2 * g]) * SCL,
                                  expf(scales[2 * g + 1]) * SCL);
    dC[g] = make_float4(colors[3 * g], colors[3 * g + 1], colors[3 * g + 2], 0.0f);

    const float FS = 1024.0f / 1024.0f;  // max_frequency / num_frequencies
#pragma unroll
    for (int k = 0; k < 4; k++) {
        float fx = (float)indices[(g * 4 + k) * 2 + 0] * FS;
        float fy = (float)indices[(g * 4 + k) * 2 + 1] * FS;
        float cx = coeffs[(g * 4 + k) * 2 + 0];
        float cy = coeffs[(g * 4 + k) * 2 + 1];
        dFK[g * 4 + k] = make_float4(fx, fy, cx, cy);
    }
}

// ---------------- render: 1 thread = 1 pixel, smem tiles of gaussians -------
__global__ __launch_bounds__(256)
void render_kernel(const float* __restrict__ x, float* __restrict__ out,
                   int N, int G) {
    __shared__ float4 sP [TILE];
    __shared__ float4 sQ [TILE];
    __shared__ float4 sC [TILE];
    __shared__ float4 sFK[TILE * 4];

    int tid = threadIdx.x;
    int i   = blockIdx.x * 256 + tid;
    float px = 0.0f, py = 0.0f;
    if (i < N) {
        float2 p = reinterpret_cast<const float2*>(x)[i];
        px = p.x; py = p.y;
    }
    u64 ppx = pk2(px, px);
    u64 ppy = pk2(py, py);
    float a0 = 0.0f, a1 = 0.0f, a2 = 0.0f;

    const ulonglong2* pP  = reinterpret_cast<const ulonglong2*>(sP);
    const ulonglong2* pQ  = reinterpret_cast<const ulonglong2*>(sQ);
    const ulonglong2* pFK = reinterpret_cast<const ulonglong2*>(sFK);

    for (int t0 = 0; t0 < G; t0 += TILE) {
        int gi = t0 + tid;
        if (gi < G) {
            sP[tid] = dP[gi];
            sQ[tid] = dQ[gi];
            sC[tid] = dC[gi];
#pragma unroll
            for (int k = 0; k < 4; k++) sFK[4 * tid + k] = dFK[4 * gi + k];
        }
        __syncthreads();

        int cnt = min(TILE, G - t0);
#pragma unroll 2
        for (int j = 0; j < cnt; j++) {
            ulonglong2 P = pP[j];            // (c,-s) , (s,c)
            ulonglong2 Q = pQ[j];            // (-ox,-oy) , (sx',sy')
            u64 t2 = fma2(ppy, P.y, Q.x);
            t2 = fma2(ppx, P.x, t2);         // (tx, ty)

            u64 a2v = mul2(t2, Q.y);
            float axv, ayv; upk2(a2v, axv, ayv);
            float m   = ayv * -ayv;
            float sqn = fmaf(axv, -axv, m);  // -((tx*sx')^2 + (ty*sy')^2)
            float gw  = ex2(sqn);            // gaussian weight

            u64 acc = 0ULL;                  // (0.0f, 0.0f)
#pragma unroll
            for (int k = 0; k < 4; k++) {
                ulonglong2 FK = pFK[4 * j + k];   // (fx,fy) , (cx,cy)
                u64 s1 = fma2(t2, FK.x, C2v);     // MAGIC + rint(t*f)   (exact)
                u64 rn = fma2(s1, NEG1v, C2v);    // -rint(t*f)          (exact)
                u64 d  = fma2(t2, FK.x, rn);      // t*f mod 1, centered (1 rounding)
                u64 ar = mul2(d, PI2v);           // radians, |ar| <= pi
                float x0, x1; upk2(ar, x0, x1);
                acc = fma2(pk2(cosap(x0), cosap(x1)), FK.y, acc);
            }

            float wx, wy; upk2(acc, wx, wy);
            float4 C = sC[j];
            float w = gw * wx * wy;
            a0 = fmaf(w, C.x, a0);
            a1 = fmaf(w, C.y, a1);
            a2 = fmaf(w, C.z, a2);
        }
        __syncthreads();
    }

    if (i < N) {
        out[3 * i + 0] = a0;
        out[3 * i + 1] = a1;
        out[3 * i + 2] = a2;
    }
}

// ---------------- harness entry ---------------------------------------------
extern "C" void kernel_launch(void* const* d_in, const int* in_sizes, int n_in,
                              void* d_out, int out_size) {
    const float* x       = (const float*)d_in[0];  // [N,2]
    const float* colors  = (const float*)d_in[1];  // [G,3]
    const float* pos     = (const float*)d_in[2];  // [G,2]
    const float* scales  = (const float*)d_in[3];  // [G,2]
    const float* rots    = (const float*)d_in[4];  // [G,1]
    const float* coeffs  = (const float*)d_in[5];  // [G,4,2]
    const int*   indices = (const int*)  d_in[6];  // [G,4,2]

    int N = in_sizes[0] / 2;
    int G = in_sizes[1] / 3;
    if (G > MAX_G) G = MAX_G;

    prep_kernel<<<(G + 255) / 256, 256>>>(colors, pos, scales, rots,
                                          coeffs, indices, G);
    render_kernel<<<(N + 255) / 256, 256>>>(x, (float*)d_out, N, G);
}

// round 6
// speedup vs baseline: 1.3895x; 1.1280x over previous
#include <cuda_runtime.h>

// ----------------------------------------------------------------------------
// PeriodicPrimitives2D — 2 pixels per thread, packed-f32x2 phase math,
// scalar cosine accumulation, MUFU cos/ex2. Targeting MUFU roofline
// (~72 SMSP-cyc per pixel-gaussian pair).
// ----------------------------------------------------------------------------

#define MAX_G 4096
#define TILE  256
#define BLK   128     // threads per block; each thread owns 2 pixels

typedef unsigned long long u64;

// Per-gaussian packed data (written by prep kernel)
__device__ float4 dP [MAX_G];       // c, -s, s, c
__device__ float4 dQ [MAX_G];       // -ox, -oy, sx', sy'
__device__ float4 dC [MAX_G];       // col0, col1, col2, 0
__device__ float4 dFK[MAX_G * 4];   // fx_k, fy_k, cx_k, cy_k

// ---------------- f32x2 packed helpers --------------------------------------
__device__ __forceinline__ u64 pk2(float a, float b) {
    u64 r;
    asm("mov.b64 %0, {%1, %2};" : "=l"(r)
        : "r"(__float_as_uint(a)), "r"(__float_as_uint(b)));
    return r;
}
__device__ __forceinline__ void upk2(u64 v, float& a, float& b) {
    unsigned int lo, hi;
    asm("mov.b64 {%0, %1}, %2;" : "=r"(lo), "=r"(hi) : "l"(v));
    a = __uint_as_float(lo);
    b = __uint_as_float(hi);
}
__device__ __forceinline__ u64 mul2(u64 a, u64 b) {
    u64 r; asm("mul.rn.f32x2 %0, %1, %2;" : "=l"(r) : "l"(a), "l"(b)); return r;
}
__device__ __forceinline__ u64 fma2(u64 a, u64 b, u64 c) {
    u64 r; asm("fma.rn.f32x2 %0, %1, %2, %3;" : "=l"(r) : "l"(a), "l"(b), "l"(c));
    return r;
}
__device__ __forceinline__ float ex2(float x) {
    float r; asm("ex2.approx.f32 %0, %1;" : "=f"(r) : "f"(x)); return r;
}
__device__ __forceinline__ float cosap(float x) {
    float r; asm("cos.approx.f32 %0, %1;" : "=f"(r) : "f"(x)); return r;
}

// Packed constants
#define C2v   0x4B4000004B400000ULL  //  1.5 * 2^23 (round-to-int magic)
#define NEG1v 0xBF800000BF800000ULL  // -1.0f
#define PI2v  0x40C90FDB40C90FDBULL  //  2*pi

// ---------------- prep: fold per-gaussian transcendentals, repack -----------
__global__ void prep_kernel(const float* __restrict__ colors,
                            const float* __restrict__ pos,
                            const float* __restrict__ scales,
                            const float* __restrict__ rots,
                            const float* __restrict__ coeffs,
                            const int*   __restrict__ indices,
                            int G) {
    int g = blockIdx.x * blockDim.x + threadIdx.x;
    if (g >= G) return;
    float s, c;
    sincosf(rots[g], &s, &c);
    float gx = pos[2 * g], gy = pos[2 * g + 1];
    float ox =  gx * c + gy * s;
    float oy = -gx * s + gy * c;
    // s' = e^scale * sqrt(0.5 * log2(e)) :  exp(-0.5*(t e^s)^2) = 2^(-(t s')^2)
    const float SCL = 0.84932180625508979f;
    dP[g] = make_float4(c, -s, s, c);
    dQ[g] = make_float4(-ox, -oy, expf(scales[2 * g]) * SCL,
                                  expf(scales[2 * g + 1]) * SCL);
    dC[g] = make_float4(colors[3 * g], colors[3 * g + 1], colors[3 * g + 2], 0.0f);

    const float FS = 1024.0f / 1024.0f;  // max_frequency / num_frequencies
#pragma unroll
    for (int k = 0; k < 4; k++) {
        float fx = (float)indices[(g * 4 + k) * 2 + 0] * FS;
        float fy = (float)indices[(g * 4 + k) * 2 + 1] * FS;
        float cx = coeffs[(g * 4 + k) * 2 + 0];
        float cy = coeffs[(g * 4 + k) * 2 + 1];
        dFK[g * 4 + k] = make_float4(fx, fy, cx, cy);
    }
}

// ---------------- render: 2 pixels/thread, smem tiles of gaussians ----------
__global__ __launch_bounds__(BLK)
void render_kernel(const float* __restrict__ x, float* __restrict__ out,
                   int N, int G) {
    __shared__ float4 sP [TILE];
    __shared__ float4 sQ [TILE];
    __shared__ float4 sC [TILE];
    __shared__ float4 sFK[TILE * 4];

    int tid  = threadIdx.x;
    int base = blockIdx.x * (2 * BLK);      // 256 pixels per block
    int i0   = base + 2 * tid;              // this thread: pixels i0, i0+1

    float pxa = 0.f, pya = 0.f, pxb = 0.f, pyb = 0.f;
    if (i0 + 1 < N) {
        float4 pp = reinterpret_cast<const float4*>(x)[i0 >> 1];
        pxa = pp.x; pya = pp.y; pxb = pp.z; pyb = pp.w;
    } else if (i0 < N) {
        float2 pp = reinterpret_cast<const float2*>(x)[i0];
        pxa = pp.x; pya = pp.y;
    }
    u64 Pxa = pk2(pxa, pxa), Pya = pk2(pya, pya);
    u64 Pxb = pk2(pxb, pxb), Pyb = pk2(pyb, pyb);

    float a0 = 0.f, a1 = 0.f, a2 = 0.f;
    float b0 = 0.f, b1 = 0.f, b2 = 0.f;

    const ulonglong2* pP  = reinterpret_cast<const ulonglong2*>(sP);
    const ulonglong2* pQ  = reinterpret_cast<const ulonglong2*>(sQ);
    const ulonglong2* pFK = reinterpret_cast<const ulonglong2*>(sFK);

    for (int t0 = 0; t0 < G; t0 += TILE) {
#pragma unroll
        for (int v = tid; v < TILE; v += BLK) {
            int gi = t0 + v;
            if (gi < G) {
                sP[v] = dP[gi];
                sQ[v] = dQ[gi];
                sC[v] = dC[gi];
#pragma unroll
                for (int k = 0; k < 4; k++) sFK[4 * v + k] = dFK[4 * gi + k];
            }
        }
        __syncthreads();

        int cnt = min(TILE, G - t0);
#pragma unroll 2
        for (int j = 0; j < cnt; j++) {
            ulonglong2 P = pP[j];            // (c,-s) , (s,c)
            ulonglong2 Q = pQ[j];            // (-ox,-oy) , (sx',sy')

            u64 ta = fma2(Pya, P.y, Q.x);
            ta = fma2(Pxa, P.x, ta);         // (txa, tya)
            u64 tb = fma2(Pyb, P.y, Q.x);
            tb = fma2(Pxb, P.x, tb);         // (txb, tyb)

            u64 ga = mul2(ta, Q.y);
            float gax, gay; upk2(ga, gax, gay);
            float gwa = ex2(fmaf(gax, -gax, gay * -gay));
            u64 gb = mul2(tb, Q.y);
            float gbx, gby; upk2(gb, gbx, gby);
            float gwb = ex2(fmaf(gbx, -gbx, gby * -gby));

            float wxa = 0.f, wya = 0.f, wxb = 0.f, wyb = 0.f;
#pragma unroll
            for (int k = 0; k < 4; k++) {
                ulonglong2 FK = pFK[4 * j + k];   // (fx,fy) , (cx,cy)
                float cx, cy; upk2(FK.y, cx, cy);

                u64 s1a = fma2(ta, FK.x, C2v);    // MAGIC + rint(t*f)  (exact)
                u64 rna = fma2(s1a, NEG1v, C2v);  // -rint(t*f)         (exact)
                u64 da  = fma2(ta, FK.x, rna);    // t*f mod 1, centered
                u64 ara = mul2(da, PI2v);
                float xa0, xa1; upk2(ara, xa0, xa1);
                wxa = fmaf(cosap(xa0), cx, wxa);
                wya = fmaf(cosap(xa1), cy, wya);

                u64 s1b = fma2(tb, FK.x, C2v);
                u64 rnb = fma2(s1b, NEG1v, C2v);
                u64 db  = fma2(tb, FK.x, rnb);
                u64 arb = mul2(db, PI2v);
                float xb0, xb1; upk2(arb, xb0, xb1);
                wxb = fmaf(cosap(xb0), cx, wxb);
                wyb = fmaf(cosap(xb1), cy, wyb);
            }

            float4 C = sC[j];
            float wa = gwa * wxa * wya;
            a0 = fmaf(wa, C.x, a0);
            a1 = fmaf(wa, C.y, a1);
            a2 = fmaf(wa, C.z, a2);
            float wb = gwb * wxb * wyb;
            b0 = fmaf(wb, C.x, b0);
            b1 = fmaf(wb, C.y, b1);
            b2 = fmaf(wb, C.z, b2);
        }
        __syncthreads();
    }

    if (i0 + 1 < N) {
        float2* o2 = reinterpret_cast<float2*>(out + 3 * i0);
        o2[0] = make_float2(a0, a1);
        o2[1] = make_float2(a2, b0);
        o2[2] = make_float2(b1, b2);
    } else if (i0 < N) {
        out[3 * i0 + 0] = a0;
        out[3 * i0 + 1] = a1;
        out[3 * i0 + 2] = a2;
    }
}

// ---------------- harness entry ---------------------------------------------
extern "C" void kernel_launch(void* const* d_in, const int* in_sizes, int n_in,
                              void* d_out, int out_size) {
    const float* x       = (const float*)d_in[0];  // [N,2]
    const float* colors  = (const float*)d_in[1];  // [G,3]
    const float* pos     = (const float*)d_in[2];  // [G,2]
    const float* scales  = (const float*)d_in[3];  // [G,2]
    const float* rots    = (const float*)d_in[4];  // [G,1]
    const float* coeffs  = (const float*)d_in[5];  // [G,4,2]
    const int*   indices = (const int*)  d_in[6];  // [G,4,2]

    int N = in_sizes[0] / 2;
    int G = in_sizes[1] / 3;
    if (G > MAX_G) G = MAX_G;

    prep_kernel<<<(G + 255) / 256, 256>>>(colors, pos, scales, rots,
                                          coeffs, indices, G);
    int pixPerBlk = 2 * BLK;
    render_kernel<<<(N + pixPerBlk - 1) / pixPerBlk, BLK>>>(x, (float*)d_out, N, G);
}